// round 14
// baseline (speedup 1.0000x reference)
#include <cuda_runtime.h>

#define NATOM 24
#define NSP 4
#define OUTW 384          // 64 radial + 320 angular
#define RADW 64
#define CPB 6             // centers per block
#define PARTS 4
#define THREADS 256       // 8 warps
#define NWARP 8
#define CHUNK 256
#define NBUCK (CPB * 10)  // 60 (center x species-pair)

__constant__ float COSZ[8] = {
     0.980785280403230449f,  0.831469612302545237f,  0.555570233019602225f,  0.195090322016128268f,
    -0.195090322016128268f, -0.555570233019602225f, -0.831469612302545237f, -0.980785280403230449f };
__constant__ float SINZ[8] = {
     0.195090322016128268f,  0.555570233019602225f,  0.831469612302545237f,  0.980785280403230449f,
     0.980785280403230449f,  0.831469612302545237f,  0.555570233019602225f,  0.195090322016128268f };

__global__ __launch_bounds__(THREADS)
void aev_kernel(const int* __restrict__ g_species,
                const float* __restrict__ g_coords,
                float* __restrict__ g_out, int M)
{
    const int bid   = blockIdx.x;
    const int m     = bid >> 2;
    const int ibase = (bid & 3) * CPB;

    __shared__ float  sc[NATOM][3];
    __shared__ int    ssp[NATOM];
    __shared__ float  sd  [CPB][NATOM];
    __shared__ float  sfcr[CPB][NATOM];
    __shared__ float4 cu  [CPB * NATOM];   // compacted: ux,uy,uz,d
    __shared__ float  cfa [CPB * NATOM];   // compacted: fca
    __shared__ int    csp [CPB * NATOM];   // compacted: species
    __shared__ int    scnt[CPB];           // live-neighbor counters
    __shared__ int    pbase[CPB + 1];      // prefix of per-center pair counts
    __shared__ float4 st1[CHUNK];          // c, s, (unused), (unused)
    __shared__ float4 st2[CHUNK];          // folded weights wf[0..3]
    __shared__ unsigned char sbkt[CHUNK];  // bucket id per staged triple
    __shared__ int    bcnt[NBUCK];         // bucket counts
    __shared__ int    bstart[NBUCK + 1];   // bucket prefix
    __shared__ int    boff[NBUCK];         // scatter cursors
    __shared__ short  order[CHUNK];        // triple indices sorted by bucket
    // FIX (R13 fault): acc is cast to float4* in the writeout; a bare float
    // array is only 4B-aligned and the R12 arrays shifted it off 16B.
    __shared__ __align__(16) float acc[CPB][OUTW];

    const int tid  = threadIdx.x;
    const int lane = tid & 31;
    const int w    = tid >> 5;

    // ---- init -----------------------------------------------------------
    if (tid < CPB) scnt[tid] = 0;
    if (tid < NATOM) {
        ssp[tid]   = g_species[m * NATOM + tid];
        sc[tid][0] = g_coords[(m * NATOM + tid) * 3 + 0];
        sc[tid][1] = g_coords[(m * NATOM + tid) * 3 + 1];
        sc[tid][2] = g_coords[(m * NATOM + tid) * 3 + 2];
    }
    for (int idx = tid; idx < CPB * OUTW; idx += THREADS)
        ((float*)acc)[idx] = 0.0f;
    __syncthreads();

    // ---- screen: flat over 144 (center, neighbor) pairs -------------------
    if (tid < CPB * NATOM) {
        int il = tid / NATOM, j = tid - il * NATOM;
        int ic = ibase + il;
        float dx = sc[j][0] - sc[ic][0];
        float dy = sc[j][1] - sc[ic][1];
        float dz = sc[j][2] - sc[ic][2];
        float d2 = dx * dx + dy * dy + dz * dz;
        bool ok = (j != ic);
        float d = ok ? sqrtf(d2) : 1.0f;
        float fca = (ok && d <= 3.5f) ? (0.5f * __cosf(0.897597901025655210f * d) + 0.5f) : 0.0f;
        float fcr = (ok && d <= 5.2f) ? (0.5f * __cosf(0.604152493782718100f * d) + 0.5f) : 0.0f;
        sd[il][j]   = d;
        sfcr[il][j] = fcr;
        if (fca > 0.0f) {
            int pos = atomicAdd(&scnt[il], 1);
            float rd = 1.0f / d;
            cu [il * NATOM + pos] = make_float4(dx * rd, dy * rd, dz * rd, d);
            cfa[il * NATOM + pos] = fca;
            csp[il * NATOM + pos] = ssp[j];
        }
    }
    __syncthreads();

    // ---- radial: flat over 2304 (pair, shift) tasks; thread 0 scans -------
    if (tid == 0) {
        int run = 0;
        #pragma unroll
        for (int il = 0; il < CPB; il++) {
            pbase[il] = run;
            int nn = scnt[il];
            run += (nn * (nn - 1)) >> 1;
        }
        pbase[CPB] = run;
    }
    #pragma unroll
    for (int k = 0; k < (CPB * NATOM * 16) / THREADS; k++) {
        int idx = k * THREADS + tid;
        int p = idx >> 4, r = idx & 15;
        int il = p / NATOM, j = p - il * NATOM;
        float fcr = sfcr[il][j];
        if (fcr > 0.0f) {
            float u = sd[il][j] - (0.9f + 0.26875f * (float)r);
            float v = 0.25f * fcr * __expf(-16.0f * u * u);
            atomicAdd(&acc[il][ssp[j] * 16 + r], v);
        }
    }
    __syncthreads();

    // ---- chunked drain: stage -> bucket-sort -> per-bucket accumulate -----
    const int NP = pbase[CPB];
    {
        const float czc = 0.5f * COSZ[lane & 7];
        const float szc = 0.5f * SINZ[lane & 7];
        const int   sel = lane >> 3;
        float* accf = (float*)acc;

        for (int chunk = 0; chunk < NP; chunk += CHUNK) {
            const int cnt = min(CHUNK, NP - chunk);

            if (tid < NBUCK) bcnt[tid] = 0;
            __syncthreads();

            // phase A: thread = triple; decode, compute, stage, count bucket
            if (tid < cnt) {
                int tg = chunk + tid;
                int il = 0;
                while (tg >= pbase[il + 1]) il++;
                int rem = tg - pbase[il];
                int nn = scnt[il];
                int a = 0, rowlen = nn - 1;
                while (rem >= rowlen) { rem -= rowlen; rowlen--; a++; }
                int b = a + 1 + rem;
                int ia = il * NATOM + a, ib = il * NATOM + b;

                int spa = csp[ia], spb = csp[ib];
                int lo = min(spa, spb), hi = max(spa, spb);
                int pidx = lo * NSP - ((lo * (lo - 1)) >> 1) + (hi - lo);
                int bkt = il * 10 + pidx;

                float4 ua = cu[ia];
                float4 ub = cu[ib];
                float c = 0.95f * (ua.x * ub.x + ua.y * ub.y + ua.z * ub.z);
                float s = sqrtf(fmaxf(0.0f, 1.0f - c * c));
                float davg = 0.5f * (ua.w + ub.w);
                float w2   = 2.0f * cfa[ia] * cfa[ib];
                float u0 = davg - 0.90f;
                float u1 = davg - 1.55f;
                float u2 = davg - 2.20f;
                float u3 = davg - 2.85f;
                float4 wf;
                wf.x = w2 * __expf(-8.0f * u0 * u0);
                wf.y = w2 * __expf(-8.0f * u1 * u1);
                wf.z = w2 * __expf(-8.0f * u2 * u2);
                wf.w = w2 * __expf(-8.0f * u3 * u3);
                st1[tid]  = make_float4(c, s, 0.f, 0.f);
                st2[tid]  = wf;
                sbkt[tid] = (unsigned char)bkt;
                atomicAdd(&bcnt[bkt], 1);
            }
            __syncthreads();

            // prefix sum over buckets (thread 0; 60 entries)
            if (tid == 0) {
                int run = 0;
                #pragma unroll
                for (int bkk = 0; bkk < NBUCK; bkk++) {
                    bstart[bkk] = run;
                    boff[bkk]   = run;
                    run += bcnt[bkk];
                }
                bstart[NBUCK] = run;
            }
            __syncthreads();

            // scatter: order[] = triple indices grouped by bucket
            if (tid < cnt) {
                int pos = atomicAdd(&boff[sbkt[tid]], 1);
                order[pos] = (short)tid;
            }
            __syncthreads();

            // phase B: warp owns buckets w, w+8, ... ; register accumulate,
            // ONE plain RMW to acc per bucket (exclusive ownership, no atomics)
            for (int wb = w; wb < NBUCK; wb += NWARP) {
                int s0 = bstart[wb], s1 = bstart[wb + 1];
                if (s0 == s1) continue;
                float rsum = 0.0f;
                for (int t = s0; t < s1; t++) {
                    int idx = order[t];              // warp-uniform broadcast
                    float4 q  = st1[idx];
                    float  wv = ((const float*)&st2[idx])[sel];
                    float cz = 0.5f + q.x * czc + q.y * szc;
                    float x = cz * cz;   // ^2
                    x = x * x;           // ^4
                    x = x * x;           // ^8
                    x = x * x;           // ^16
                    x = x * x;           // ^32
                    rsum = fmaf(x, wv, rsum);
                }
                int il = wb / 10, pidx = wb - il * 10;
                int off = il * OUTW + RADW + pidx * 32 + lane;
                accf[off] += rsum;
            }
            __syncthreads();
        }
    }

    // ---- writeout (float4) -----------------------------------------------
    {
        const float4* src = (const float4*)acc;
        float4* dstg = (float4*)(g_out + ((size_t)m * NATOM + ibase) * OUTW);
        #pragma unroll
        for (int idx = tid; idx < CPB * OUTW / 4; idx += THREADS)
            dstg[idx] = src[idx];
    }
}

extern "C" void kernel_launch(void* const* d_in, const int* in_sizes, int n_in,
                              void* d_out, int out_size)
{
    const int*   species = (const int*)d_in[0];
    const float* coords  = (const float*)d_in[1];
    int M = in_sizes[0] / NATOM;
    aev_kernel<<<M * PARTS, THREADS>>>(species, coords, (float*)d_out, M);
}

// round 15
// speedup vs baseline: 1.1194x; 1.1194x over previous
#include <cuda_runtime.h>

#define NATOM 24
#define NSP 4
#define OUTW 384          // 64 radial + 320 angular
#define RADW 64
#define CPB 3             // centers per block
#define PARTS 8
#define THREADS 128       // 4 warps
#define NWARP 4
#define CHUNK 128

__constant__ float COSZ[8] = {
     0.980785280403230449f,  0.831469612302545237f,  0.555570233019602225f,  0.195090322016128268f,
    -0.195090322016128268f, -0.555570233019602225f, -0.831469612302545237f, -0.980785280403230449f };
__constant__ float SINZ[8] = {
     0.195090322016128268f,  0.555570233019602225f,  0.831469612302545237f,  0.980785280403230449f,
     0.980785280403230449f,  0.831469612302545237f,  0.555570233019602225f,  0.195090322016128268f };

#define PACK_F32X2(out, lo, hi) \
    asm("mov.b64 %0, {%1, %2};" : "=l"(out) : "f"(lo), "f"(hi))
#define UNPACK_F32X2(lo, hi, in) \
    asm("mov.b64 {%0, %1}, %2;" : "=f"(lo), "=f"(hi) : "l"(in))
#define MUL_F32X2(out, a, b) \
    asm("mul.rn.f32x2 %0, %1, %2;" : "=l"(out) : "l"(a), "l"(b))

__global__ __launch_bounds__(THREADS)
void aev_kernel(const int* __restrict__ g_species,
                const float* __restrict__ g_coords,
                float* __restrict__ g_out, int M)
{
    const int bid   = blockIdx.x;
    const int m     = bid >> 3;
    const int ibase = (bid & 7) * CPB;

    __shared__ float  sc[NATOM][3];
    __shared__ int    ssp[NATOM];
    __shared__ float  sd  [CPB][NATOM];
    __shared__ float  sfcr[CPB][NATOM];
    __shared__ float4 cu  [CPB * NATOM];   // compacted: ux,uy,uz,d
    __shared__ float  cfa [CPB * NATOM];   // compacted: fca
    __shared__ int    csp [CPB * NATOM];   // compacted: species
    __shared__ int    scnt[CPB];           // live-neighbor counters
    __shared__ int    pbase[CPB + 1];      // prefix of per-center pair counts
    __shared__ float4 st1[CHUNK + 1];      // c, s, off(bits), pad
    __shared__ float4 st2[CHUNK + 1];      // folded weights wf[0..3]
    __shared__ __align__(16) float acc[CPB][OUTW];

    const int tid  = threadIdx.x;
    const int lane = tid & 31;
    const int w    = tid >> 5;

    // ---- init -----------------------------------------------------------
    if (tid < CPB) scnt[tid] = 0;
    if (tid < NATOM) {
        ssp[tid]   = g_species[m * NATOM + tid];
        sc[tid][0] = g_coords[(m * NATOM + tid) * 3 + 0];
        sc[tid][1] = g_coords[(m * NATOM + tid) * 3 + 1];
        sc[tid][2] = g_coords[(m * NATOM + tid) * 3 + 2];
    }
    for (int idx = tid; idx < CPB * OUTW; idx += THREADS)
        ((float*)acc)[idx] = 0.0f;
    __syncthreads();

    // ---- screen: flat over 72 (center, neighbor) pairs --------------------
    if (tid < CPB * NATOM) {
        int il = tid / NATOM, j = tid - il * NATOM;
        int ic = ibase + il;
        float dx = sc[j][0] - sc[ic][0];
        float dy = sc[j][1] - sc[ic][1];
        float dz = sc[j][2] - sc[ic][2];
        float d2 = dx * dx + dy * dy + dz * dz;
        bool ok = (j != ic);
        float d = ok ? sqrtf(d2) : 1.0f;
        float fca = (ok && d <= 3.5f) ? (0.5f * __cosf(0.897597901025655210f * d) + 0.5f) : 0.0f;
        float fcr = (ok && d <= 5.2f) ? (0.5f * __cosf(0.604152493782718100f * d) + 0.5f) : 0.0f;
        sd[il][j]   = d;
        sfcr[il][j] = fcr;
        if (fca > 0.0f) {
            int pos = atomicAdd(&scnt[il], 1);
            float rd = 1.0f / d;
            cu [il * NATOM + pos] = make_float4(dx * rd, dy * rd, dz * rd, d);
            cfa[il * NATOM + pos] = fca;
            csp[il * NATOM + pos] = ssp[j];
        }
    }
    __syncthreads();

    // ---- radial: flat over 1152 (pair, shift) tasks; thread 0 scans -------
    if (tid == 0) {
        int run = 0;
        #pragma unroll
        for (int il = 0; il < CPB; il++) {
            pbase[il] = run;
            int nn = scnt[il];
            run += (nn * (nn - 1)) >> 1;
        }
        pbase[CPB] = run;
    }
    #pragma unroll
    for (int k = 0; k < (CPB * NATOM * 16) / THREADS; k++) {
        int idx = k * THREADS + tid;
        int p = idx >> 4, r = idx & 15;
        int il = p / NATOM, j = p - il * NATOM;
        float fcr = sfcr[il][j];
        if (fcr > 0.0f) {
            float u = sd[il][j] - (0.9f + 0.26875f * (float)r);
            float v = 0.25f * fcr * __expf(-16.0f * u * u);
            atomicAdd(&acc[il][ssp[j] * 16 + r], v);
        }
    }
    __syncthreads();

    // ---- chunked drain: phase A (decode+stage), phase B (outputs) ---------
    const int NP = pbase[CPB];
    {
        const float czc = 0.5f * COSZ[lane & 7];
        const float szc = 0.5f * SINZ[lane & 7];
        const int   sel = lane >> 3;
        float* accf = (float*)acc;

        for (int chunk = 0; chunk < NP; chunk += CHUNK) {
            const int cnt = min(CHUNK, NP - chunk);

            // phase A: thread = triple; decode triangular index in-place
            if (tid < cnt) {
                int tg = chunk + tid;
                int il = 0;
                while (tg >= pbase[il + 1]) il++;
                int rem = tg - pbase[il];
                int nn = scnt[il];
                int a = 0, rowlen = nn - 1;
                while (rem >= rowlen) { rem -= rowlen; rowlen--; a++; }
                int b = a + 1 + rem;
                int ia = il * NATOM + a, ib = il * NATOM + b;

                int spa = csp[ia], spb = csp[ib];
                int lo = min(spa, spb), hi = max(spa, spb);
                int pidx = lo * NSP - ((lo * (lo - 1)) >> 1) + (hi - lo);
                int off = il * OUTW + RADW + pidx * 32;

                float4 ua = cu[ia];
                float4 ub = cu[ib];
                float c = 0.95f * (ua.x * ub.x + ua.y * ub.y + ua.z * ub.z);
                float s = sqrtf(fmaxf(0.0f, 1.0f - c * c));
                float davg = 0.5f * (ua.w + ub.w);
                float w2   = 2.0f * cfa[ia] * cfa[ib];
                float u0 = davg - 0.90f;
                float u1 = davg - 1.55f;
                float u2 = davg - 2.20f;
                float u3 = davg - 2.85f;
                float4 wf;
                wf.x = w2 * __expf(-8.0f * u0 * u0);
                wf.y = w2 * __expf(-8.0f * u1 * u1);
                wf.z = w2 * __expf(-8.0f * u2 * u2);
                wf.w = w2 * __expf(-8.0f * u3 * u3);
                st1[tid] = make_float4(c, s, __int_as_float(off), 0.f);
                st2[tid] = wf;
            }
            // zero pad entry so phase B can run an even, branch-free count
            if (tid == cnt) {
                st1[tid] = make_float4(0.f, 0.f, __int_as_float(0), 0.f);
                st2[tid] = make_float4(0.f, 0.f, 0.f, 0.f);
            }
            __syncthreads();

            const int cntp = (cnt + 1) & ~1;
            // phase B: warp = 2 triples per iteration, packed f32x2 ^32 chain
            for (int t = 2 * w; t < cntp; t += 2 * NWARP) {
                float4 q0 = st1[t];
                float4 q1 = st1[t + 1];
                float wv0 = ((const float*)&st2[t])[sel];
                float wv1 = ((const float*)&st2[t + 1])[sel];
                float cz0 = 0.5f + q0.x * czc + q0.y * szc;
                float cz1 = 0.5f + q1.x * czc + q1.y * szc;
                unsigned long long P, xb;
                PACK_F32X2(P, cz0, cz1);
                MUL_F32X2(xb, P, P);     // ^2
                MUL_F32X2(xb, xb, xb);   // ^4
                MUL_F32X2(xb, xb, xb);   // ^8
                MUL_F32X2(xb, xb, xb);   // ^16
                MUL_F32X2(xb, xb, xb);   // ^32
                float x0, x1;
                UNPACK_F32X2(x0, x1, xb);
                atomicAdd(&accf[__float_as_int(q0.z) + lane], x0 * wv0);
                atomicAdd(&accf[__float_as_int(q1.z) + lane], x1 * wv1);
            }
            __syncthreads();
        }
    }

    // ---- writeout (float4) -----------------------------------------------
    {
        const float4* src = (const float4*)acc;
        float4* dstg = (float4*)(g_out + ((size_t)m * NATOM + ibase) * OUTW);
        for (int idx = tid; idx < CPB * OUTW / 4; idx += THREADS)
            dstg[idx] = src[idx];
    }
}

extern "C" void kernel_launch(void* const* d_in, const int* in_sizes, int n_in,
                              void* d_out, int out_size)
{
    const int*   species = (const int*)d_in[0];
    const float* coords  = (const float*)d_in[1];
    int M = in_sizes[0] / NATOM;
    aev_kernel<<<M * PARTS, THREADS>>>(species, coords, (float*)d_out, M);
}

// round 16
// speedup vs baseline: 1.1364x; 1.0152x over previous
#include <cuda_runtime.h>

#define NATOM 24
#define NSP 4
#define OUTW 384          // 64 radial + 320 angular
#define RADW 64
#define CPB 6             // centers per block
#define PARTS 4
#define THREADS 256       // 8 warps
#define NWARP 8
#define CHUNK 256
#define MAXTRI (CPB * 253)

__constant__ float COSZ[8] = {
     0.980785280403230449f,  0.831469612302545237f,  0.555570233019602225f,  0.195090322016128268f,
    -0.195090322016128268f, -0.555570233019602225f, -0.831469612302545237f, -0.980785280403230449f };
__constant__ float SINZ[8] = {
     0.195090322016128268f,  0.555570233019602225f,  0.831469612302545237f,  0.980785280403230449f,
     0.980785280403230449f,  0.831469612302545237f,  0.555570233019602225f,  0.195090322016128268f };

#define PACK_F32X2(out, lo, hi) \
    asm("mov.b64 %0, {%1, %2};" : "=l"(out) : "f"(lo), "f"(hi))
#define UNPACK_F32X2(lo, hi, in) \
    asm("mov.b64 {%0, %1}, %2;" : "=f"(lo), "=f"(hi) : "l"(in))
#define MUL_F32X2(out, a, b) \
    asm("mul.rn.f32x2 %0, %1, %2;" : "=l"(out) : "l"(a), "l"(b))

__global__ __launch_bounds__(THREADS)
void aev_kernel(const int* __restrict__ g_species,
                const float* __restrict__ g_coords,
                float* __restrict__ g_out, int M)
{
    const int bid   = blockIdx.x;
    const int m     = bid >> 2;
    const int ibase = (bid & 3) * CPB;

    __shared__ float    sc[NATOM][3];
    __shared__ int      ssp[NATOM];
    __shared__ float    sd  [CPB][NATOM];
    __shared__ float    sfcr[CPB][NATOM];
    __shared__ float4   cu  [CPB * NATOM];   // compacted: ux,uy,uz (pre-scaled by sqrt(.95)), d
    __shared__ float    cfa [CPB * NATOM];
    __shared__ int      csp [CPB * NATOM];
    __shared__ unsigned triples[MAXTRI];     // (off<<16)|(ia<<8)|ib
    __shared__ int      tcnt;
    __shared__ float4   st1[CHUNK + 1];      // c, s, off(bits), pad
    __shared__ float4   st2[CHUNK + 1];      // folded weights wf[0..3]
    __shared__ __align__(16) float acc[CPB][OUTW];

    const int tid  = threadIdx.x;
    const int lane = tid & 31;
    const int w    = tid >> 5;

    // ---- init -----------------------------------------------------------
    if (tid == 0) tcnt = 0;
    if (tid < NATOM) {
        ssp[tid]   = g_species[m * NATOM + tid];
        sc[tid][0] = g_coords[(m * NATOM + tid) * 3 + 0];
        sc[tid][1] = g_coords[(m * NATOM + tid) * 3 + 1];
        sc[tid][2] = g_coords[(m * NATOM + tid) * 3 + 2];
    }
    for (int idx = tid; idx < CPB * OUTW; idx += THREADS)
        ((float*)acc)[idx] = 0.0f;
    __syncthreads();

    // ---- screen + compact: warps 0..5, lane = neighbor j ------------------
    if (w < CPB) {
        const int ic = ibase + w;
        bool  live = false;
        float fca = 0.f, d = 1.f, dx = 0.f, dy = 0.f, dz = 0.f;
        if (lane < NATOM) {
            int j = lane;
            dx = sc[j][0] - sc[ic][0];
            dy = sc[j][1] - sc[ic][1];
            dz = sc[j][2] - sc[ic][2];
            float d2 = dx * dx + dy * dy + dz * dz;
            bool ok = (j != ic);
            d = ok ? sqrtf(d2) : 1.0f;
            fca       = (ok && d <= 3.5f) ? (0.5f * __cosf(0.897597901025655210f * d) + 0.5f) : 0.0f;
            float fcr = (ok && d <= 5.2f) ? (0.5f * __cosf(0.604152493782718100f * d) + 0.5f) : 0.0f;
            sd[w][j]   = d;
            sfcr[w][j] = fcr;
            live = (fca > 0.0f);
        }
        unsigned mask = __ballot_sync(0xffffffffu, live);
        int nn = __popc(mask);
        if (live) {
            int pos = __popc(mask & ((1u << lane) - 1u));
            // fold sqrt(0.95) into the unit vector so c = dot() directly
            float rd = 0.97467943448089633f / d;
            cu [w * NATOM + pos] = make_float4(dx * rd, dy * rd, dz * rd, d);
            cfa[w * NATOM + pos] = fca;
            csp[w * NATOM + pos] = ssp[lane];
        }
        __syncwarp();

        // emit triples (precompute acc offset incl. pair-species index)
        int npairs = (nn * (nn - 1)) >> 1;
        int base = 0;
        if (lane == 0 && npairs > 0) base = atomicAdd(&tcnt, npairs);
        base = __shfl_sync(0xffffffffu, base, 0);
        for (int idx = lane; idx < npairs; idx += 32) {
            int a = 0, rem = idx, rowlen = nn - 1;
            while (rem >= rowlen) { rem -= rowlen; rowlen--; a++; }
            int b = a + 1 + rem;
            int ia = w * NATOM + a, ib = w * NATOM + b;
            int spa = csp[ia], spb = csp[ib];
            int lo = min(spa, spb), hi = max(spa, spb);
            int pidx = lo * NSP - ((lo * (lo - 1)) >> 1) + (hi - lo);
            unsigned off = (unsigned)(w * OUTW + RADW + pidx * 32);
            triples[base + idx] = (off << 16) | ((unsigned)ia << 8) | (unsigned)ib;
        }
    }
    __syncthreads();

    // ---- radial: flat over 2304 (pair, shift) tasks on ALL 8 warps --------
    #pragma unroll
    for (int k = 0; k < (CPB * NATOM * 16) / THREADS; k++) {
        int idx = k * THREADS + tid;
        int p = idx >> 4, r = idx & 15;
        int il = p / NATOM, j = p - il * NATOM;
        float fcr = sfcr[il][j];
        if (fcr > 0.0f) {
            float u = sd[il][j] - (0.9f + 0.26875f * (float)r);
            float v = 0.25f * fcr * __expf(-16.0f * u * u);
            atomicAdd(&acc[il][ssp[j] * 16 + r], v);
        }
    }
    __syncthreads();

    // ---- chunked block-wide drain -----------------------------------------
    const int NP = tcnt;
    {
        const float czc = 0.5f * COSZ[lane & 7];
        const float szc = 0.5f * SINZ[lane & 7];
        const int   sel = lane >> 3;
        float* accLane = ((float*)acc) + lane;   // hoisted lane base

        for (int chunk = 0; chunk < NP; chunk += CHUNK) {
            const int cnt = min(CHUNK, NP - chunk);

            // phase A: thread = triple
            if (tid < cnt) {
                unsigned tw = triples[chunk + tid];
                int ib  = (int)(tw & 255u);
                int ia  = (int)((tw >> 8) & 255u);
                int off = (int)(tw >> 16);
                float4 ua = cu[ia];
                float4 ub = cu[ib];
                float c = ua.x * ub.x + ua.y * ub.y + ua.z * ub.z;  // 0.95*cos
                float s = sqrtf(fmaxf(0.0f, 1.0f - c * c));
                float davg = 0.5f * (ua.w + ub.w);
                float w2   = 2.0f * cfa[ia] * cfa[ib];
                float u0 = davg - 0.90f;
                float u1 = davg - 1.55f;
                float u2 = davg - 2.20f;
                float u3 = davg - 2.85f;
                float4 wf;
                wf.x = w2 * __expf(-8.0f * u0 * u0);
                wf.y = w2 * __expf(-8.0f * u1 * u1);
                wf.z = w2 * __expf(-8.0f * u2 * u2);
                wf.w = w2 * __expf(-8.0f * u3 * u3);
                st1[tid] = make_float4(c, s, __int_as_float(off), 0.f);
                st2[tid] = wf;
            }
            if (tid == cnt) {   // zero pad so phase B runs an even count
                st1[tid] = make_float4(0.f, 0.f, __int_as_float(0), 0.f);
                st2[tid] = make_float4(0.f, 0.f, 0.f, 0.f);
            }
            __syncthreads();

            const int cntp = (cnt + 1) & ~1;
            // phase B: warp = 2 triples/iter, packed f32x2 ^32 chain
            for (int t = 2 * w; t < cntp; t += 2 * NWARP) {
                float4 q0 = st1[t];
                float4 q1 = st1[t + 1];
                float wv0 = ((const float*)&st2[t])[sel];
                float wv1 = ((const float*)&st2[t + 1])[sel];
                float cz0 = 0.5f + q0.x * czc + q0.y * szc;
                float cz1 = 0.5f + q1.x * czc + q1.y * szc;
                unsigned long long P, xb;
                PACK_F32X2(P, cz0, cz1);
                MUL_F32X2(xb, P, P);     // ^2
                MUL_F32X2(xb, xb, xb);   // ^4
                MUL_F32X2(xb, xb, xb);   // ^8
                MUL_F32X2(xb, xb, xb);   // ^16
                MUL_F32X2(xb, xb, xb);   // ^32
                float x0, x1;
                UNPACK_F32X2(x0, x1, xb);
                atomicAdd(accLane + __float_as_int(q0.z), x0 * wv0);
                atomicAdd(accLane + __float_as_int(q1.z), x1 * wv1);
            }
            __syncthreads();
        }
    }

    // ---- writeout (float4) -----------------------------------------------
    {
        const float4* src = (const float4*)acc;
        float4* dstg = (float4*)(g_out + ((size_t)m * NATOM + ibase) * OUTW);
        #pragma unroll
        for (int idx = tid; idx < CPB * OUTW / 4; idx += THREADS)
            dstg[idx] = src[idx];
    }
}

extern "C" void kernel_launch(void* const* d_in, const int* in_sizes, int n_in,
                              void* d_out, int out_size)
{
    const int*   species = (const int*)d_in[0];
    const float* coords  = (const float*)d_in[1];
    int M = in_sizes[0] / NATOM;
    aev_kernel<<<M * PARTS, THREADS>>>(species, coords, (float*)d_out, M);
}